// round 14
// baseline (speedup 1.0000x reference)
#include <cuda_runtime.h>
#include <math.h>

// ============================================================================
// GAT 2-layer forward, exact-math O(n log n) reformulation.
// softmax_j(LeakyReLU(s_i + d_j)) @ V via sorted-d tables:
//   P = forward prefix of e^{d-dmax}*v ; Q = reverse suffix of e^{0.2(d-dmax)}*v
// R14: R13 base. Single delta: scan tile TS 128->64, NT 32->64 (shorter serial
//      chains, 2x block parallelism in the latency-bound scan stage).
// ============================================================================

#define NB 4
#define NN 4096
#define EPSN 1e-5f
#define NT 64      // scan tiles per chain
#define TS 64      // scan tile size (NT*TS == NN)
#define NSLAB 16   // layer-0 stats slabs

template<int L> struct LP {
  static constexpr int CIN  = (L == 0) ? 64 : 128;
  static constexpr int H    = (L == 0) ? 4 : 1;
  static constexpr int K    = (L == 0) ? 32 : 64;
  static constexpr int COUT = H * K;
  static constexpr int SL   = (L == 0) ? NSLAB : 32;  // stats slabs
};

// ---------------- scratch (device globals; no allocation allowed) ----------
__device__ float  g_part0[NB * NSLAB * 64 * 2];
__device__ float  g_part1[NB * 32 * 128 * 2];
__device__ float  g_w0p[NB * 64 * 128], g_t0[NB * 128];
__device__ float  g_w1p[NB * 128 * 64], g_t1[NB * 64];
__device__ float  g_feat0[16 * NN * 32];
__device__ float  g_feat1[4 * NN * 64];
__device__ float  g_featS0[16 * NN * 32];
__device__ float  g_featS1[4 * NN * 64];
__device__ float  g_ssrc0[16 * NN], g_sdst0[16 * NN];
__device__ float  g_ssrc1[4 * NN],  g_sdst1[4 * NN];
__device__ float  g_sortd0[16 * NN];
__device__ int    g_perm0[16 * NN];
__device__ float  g_sortd1[4 * NN];
__device__ int    g_perm1[4 * NN];
__device__ float  g_dmax0[16], g_dmax1[4];
__device__ float  g_wP0[16 * NN], g_wQ0[16 * NN];
__device__ float  g_wP1[4 * NN],  g_wQ1[4 * NN];
__device__ float  g_ts0[32 * NT * 33];
__device__ float  g_ts1[8 * NT * 65];
__device__ float  g_pref0[(size_t)16 * 2 * (NN + 1) * 33];
__device__ float  g_pref1[(size_t)4  * 2 * (NN + 1) * 65];
__device__ float  g_cat[(size_t)NB * NN * 128];

// ---------------- layer-0 instance-norm stats: slab partials ---------------
__global__ void stats_part0_kernel(const float* __restrict__ x) {
  constexpr int C = 64;
  constexpr int RP = 256 / C;  // 4
  int b = blockIdx.x, slab = blockIdx.y;
  int c = threadIdx.x % C, rr = threadIdx.x / C;
  const float* p = x + ((size_t)b * NN + (size_t)slab * 256) * C;
  float s = 0.f, s2 = 0.f;
  for (int i = rr; i < 256; i += RP) {
    float v = p[(size_t)i * C + c];
    s += v; s2 = fmaf(v, v, s2);
  }
  __shared__ float sh[256], sh2[256];
  sh[threadIdx.x] = s; sh2[threadIdx.x] = s2;
  __syncthreads();
  if (rr == 0) {
    float S = s, S2 = s2;
    #pragma unroll
    for (int j = 1; j < RP; ++j) { S += sh[j * C + c]; S2 += sh2[j * C + c]; }
    size_t o = (((size_t)b * NSLAB + slab) * C + c) * 2;
    g_part0[o] = S; g_part0[o + 1] = S2;
  }
}

// ---------------- combine stats + fold instance-norm into weights ----------
template<int L>
__global__ void fold_kernel(const float* __restrict__ w) {
  constexpr int CIN = LP<L>::CIN, K = LP<L>::K, COUT = LP<L>::COUT, SL = LP<L>::SL;
  const float* part = (L == 0) ? g_part0 : g_part1;
  float* wp = (L == 0) ? g_w0p : g_w1p;
  float* tv = (L == 0) ? g_t0 : g_t1;
  __shared__ float mu[CIN], rs[CIN];
  int b = blockIdx.x, tid = threadIdx.x;
  if (tid < CIN) {
    double S = 0.0, S2 = 0.0;
    for (int slab = 0; slab < SL; ++slab) {
      size_t o = (((size_t)b * SL + slab) * CIN + tid) * 2;
      S += (double)part[o]; S2 += (double)part[o + 1];
    }
    double mean = S / NN;
    double var = S2 / NN - mean * mean;
    mu[tid] = (float)mean;
    rs[tid] = (float)(1.0 / sqrt(var + (double)EPSN));
  }
  __syncthreads();
  if (tid < COUT) {
    int h = tid / K, k = tid % K;
    float acc = 0.f;
    for (int c = 0; c < CIN; ++c) {
      float wv  = w[((size_t)h * CIN + c) * K + k];
      float wpv = wv * rs[c];
      wp[((size_t)b * CIN + c) * COUT + tid] = wpv;
      acc = fmaf(mu[c], wpv, acc);
    }
    tv[b * COUT + tid] = acc;
  }
}

// ---------------- GEMM (float4-x register-tiled) + fused s_src/s_dst -------
template<int L>
__global__ void gemm_kernel(const float* __restrict__ xext,
                            const float* __restrict__ a_src,
                            const float* __restrict__ a_dst) {
  constexpr int CIN = LP<L>::CIN, H = LP<L>::H, K = LP<L>::K, COUT = LP<L>::COUT;
  constexpr int ROWS = (L == 0) ? 64 : 32;
  constexpr int NC = COUT / 4;
  constexpr int NR = 256 / NC;
  constexpr int RT = ROWS / NR;
  constexpr int G  = NC / H;
  const float* x  = (L == 0) ? xext : g_cat;
  const float* wp = (L == 0) ? g_w0p : g_w1p;
  const float* tv = (L == 0) ? g_t0 : g_t1;
  float* feat = (L == 0) ? g_feat0 : g_feat1;
  float* ssrc = (L == 0) ? g_ssrc0 : g_ssrc1;
  float* sdst = (L == 0) ? g_sdst0 : g_sdst1;
  __shared__ float ws[CIN * COUT];
  __shared__ float xs[ROWS * CIN];
  int b = blockIdx.x, bt = blockIdx.y;
  int tid = threadIdx.x;
  const float4* wsrc = (const float4*)(wp + (size_t)b * CIN * COUT);
  for (int i = tid; i < CIN * COUT / 4; i += 256) ((float4*)ws)[i] = wsrc[i];
  const float4* xsrc = (const float4*)(x + ((size_t)b * NN + (size_t)bt * ROWS) * CIN);
  for (int i = tid; i < ROWS * CIN / 4; i += 256) ((float4*)xs)[i] = xsrc[i];
  __syncthreads();
  int tc = tid % NC, tr = tid / NC;
  int col0 = tc * 4, r0 = tr * RT;
  float4 tv4 = *(const float4*)(tv + b * COUT + col0);
  float acc[RT][4];
  #pragma unroll
  for (int i = 0; i < RT; ++i) {
    acc[i][0] = -tv4.x; acc[i][1] = -tv4.y; acc[i][2] = -tv4.z; acc[i][3] = -tv4.w;
  }
  const float4* wsv = (const float4*)ws;
  const float4* xsv = (const float4*)xs;
  #pragma unroll 4
  for (int c = 0; c < CIN; c += 4) {
    float4 w0 = wsv[(c + 0) * NC + tc];
    float4 w1 = wsv[(c + 1) * NC + tc];
    float4 w2 = wsv[(c + 2) * NC + tc];
    float4 w3 = wsv[(c + 3) * NC + tc];
    #pragma unroll
    for (int i = 0; i < RT; ++i) {
      float4 xv = xsv[(r0 + i) * (CIN / 4) + (c >> 2)];
      acc[i][0] = fmaf(xv.x, w0.x, acc[i][0]);
      acc[i][1] = fmaf(xv.x, w0.y, acc[i][1]);
      acc[i][2] = fmaf(xv.x, w0.z, acc[i][2]);
      acc[i][3] = fmaf(xv.x, w0.w, acc[i][3]);
      acc[i][0] = fmaf(xv.y, w1.x, acc[i][0]);
      acc[i][1] = fmaf(xv.y, w1.y, acc[i][1]);
      acc[i][2] = fmaf(xv.y, w1.z, acc[i][2]);
      acc[i][3] = fmaf(xv.y, w1.w, acc[i][3]);
      acc[i][0] = fmaf(xv.z, w2.x, acc[i][0]);
      acc[i][1] = fmaf(xv.z, w2.y, acc[i][1]);
      acc[i][2] = fmaf(xv.z, w2.z, acc[i][2]);
      acc[i][3] = fmaf(xv.z, w2.w, acc[i][3]);
      acc[i][0] = fmaf(xv.w, w3.x, acc[i][0]);
      acc[i][1] = fmaf(xv.w, w3.y, acc[i][1]);
      acc[i][2] = fmaf(xv.w, w3.z, acc[i][2]);
      acc[i][3] = fmaf(xv.w, w3.w, acc[i][3]);
    }
  }
  int h = col0 / K, k0 = col0 % K;
  float4 as4 = *(const float4*)(a_src + col0);
  float4 ad4 = *(const float4*)(a_dst + col0);
  int nbase = bt * ROWS + r0;
  float* fo = feat + (((size_t)b * H + h) * NN + nbase) * K + k0;
  size_t sbase = ((size_t)b * H + h) * NN + nbase;
  #pragma unroll
  for (int i = 0; i < RT; ++i) {
    *(float4*)(fo + (size_t)i * K) = make_float4(acc[i][0], acc[i][1], acc[i][2], acc[i][3]);
    float s1 = acc[i][0] * as4.x + acc[i][1] * as4.y + acc[i][2] * as4.z + acc[i][3] * as4.w;
    float s2 = acc[i][0] * ad4.x + acc[i][1] * ad4.y + acc[i][2] * ad4.z + acc[i][3] * ad4.w;
    #pragma unroll
    for (int off = 1; off < G; off <<= 1) {
      s1 += __shfl_xor_sync(0xffffffffu, s1, off);
      s2 += __shfl_xor_sync(0xffffffffu, s2, off);
    }
    if ((tc & (G - 1)) == 0) {
      ssrc[sbase + i] = s1;
      sdst[sbase + i] = s2;
    }
  }
}

// ---------------- single-pass counting sort (4096 buckets, 1024 thr) -------
template<int L>
__global__ void sort_kernel() {
  constexpr int BT = 1024, IPT = NN / BT;  // 4
  const float* sdstA = (L == 0) ? g_sdst0 : g_sdst1;
  float* sortd = (L == 0) ? g_sortd0 : g_sortd1;
  int*   perm  = (L == 0) ? g_perm0 : g_perm1;
  float* wP = (L == 0) ? g_wP0 : g_wP1;
  float* wQ = (L == 0) ? g_wQ0 : g_wQ1;
  float* dmaxA = (L == 0) ? g_dmax0 : g_dmax1;

  __shared__ int   cnt[NN];
  __shared__ int   perm_s[NN];
  __shared__ float wred[64];
  __shared__ int   wsum[32];
  __shared__ float s_mn, s_mx;

  int bh = blockIdx.x;
  int tid = threadIdx.x, lane = tid & 31, wid = tid >> 5;
  const float* src = sdstA + (size_t)bh * NN;

  float d[IPT];
  int base = tid * IPT;
  #pragma unroll
  for (int i = 0; i < IPT; ++i) d[i] = src[base + i];

  float mn = d[0], mx = d[0];
  #pragma unroll
  for (int i = 1; i < IPT; ++i) { mn = fminf(mn, d[i]); mx = fmaxf(mx, d[i]); }
  #pragma unroll
  for (int o = 16; o; o >>= 1) {
    mn = fminf(mn, __shfl_xor_sync(0xffffffffu, mn, o));
    mx = fmaxf(mx, __shfl_xor_sync(0xffffffffu, mx, o));
  }
  if (lane == 0) { wred[wid] = mn; wred[wid + 32] = mx; }
  for (int i = tid; i < NN; i += BT) cnt[i] = 0;
  __syncthreads();
  if (tid == 0) {
    float m1 = wred[0], m2 = wred[32];
    #pragma unroll
    for (int i = 1; i < 32; ++i) { m1 = fminf(m1, wred[i]); m2 = fmaxf(m2, wred[i + 32]); }
    s_mn = m1; s_mx = m2;
    dmaxA[bh] = m2;
  }
  __syncthreads();
  float dmax = s_mx;
  float scale = (float)(NN - 1) / fmaxf(s_mx - s_mn, 1e-30f);

  int bkt[IPT];
  #pragma unroll
  for (int i = 0; i < IPT; ++i) {
    int bb = (int)((dmax - d[i]) * scale);
    bkt[i] = min(max(bb, 0), NN - 1);
    atomicAdd(&cnt[bkt[i]], 1);
  }
  __syncthreads();

  int base4 = tid * IPT;
  int c4[IPT]; int tsm = 0;
  #pragma unroll
  for (int j = 0; j < IPT; ++j) { c4[j] = cnt[base4 + j]; tsm += c4[j]; }
  int pre = tsm;
  #pragma unroll
  for (int o = 1; o < 32; o <<= 1) {
    int nv = __shfl_up_sync(0xffffffffu, pre, o);
    if (lane >= o) pre += nv;
  }
  pre -= tsm;
  if (lane == 31) wsum[wid] = pre + tsm;
  __syncthreads();
  if (tid < 32) {
    int v = wsum[tid];
    int iv = v;
    #pragma unroll
    for (int o = 1; o < 32; o <<= 1) {
      int nv = __shfl_up_sync(0xffffffffu, iv, o);
      if (tid >= o) iv += nv;
    }
    wsum[tid] = iv - v;
  }
  __syncthreads();
  int run = wsum[wid] + pre;
  #pragma unroll
  for (int j = 0; j < IPT; ++j) { cnt[base4 + j] = run; run += c4[j]; }
  __syncthreads();

  #pragma unroll
  for (int i = 0; i < IPT; ++i) {
    int r = atomicAdd(&cnt[bkt[i]], 1);
    perm_s[r] = base + i;
  }
  __syncthreads();

  for (int r = tid; r < NN; r += BT) {
    int p = perm_s[r];
    float dv = src[p];
    size_t o = (size_t)bh * NN + r;
    sortd[o] = dv;
    perm[o]  = p;
    float e = dv - dmax;
    wP[o] = expf(e);
    wQ[o] = expf(0.2f * e);
  }
}

// ---------------- scan pass A (512 thr): gather -> smem, sums, write featS -
template<int L>
__global__ void scanA_kernel() {
  constexpr int K = LP<L>::K;
  constexpr int K4 = K / 4;
  constexpr int RS = 512 / K;  // 16 / 8
  const float* feat = (L == 0) ? g_feat0 : g_feat1;
  const int*   perm = (L == 0) ? g_perm0 : g_perm1;
  const float* wPg = (L == 0) ? g_wP0 : g_wP1;
  const float* wQg = (L == 0) ? g_wQ0 : g_wQ1;
  float* featS = (L == 0) ? g_featS0 : g_featS1;
  float* tsum = (L == 0) ? g_ts0 : g_ts1;

  __shared__ float vs[TS * K];
  __shared__ float wPs[TS], wQs[TS];
  __shared__ int pm[TS];
  __shared__ float redP[512], redQ[512];

  int bh = blockIdx.x, tile = blockIdx.y, pos0 = tile * TS;
  int tid = threadIdx.x;
  if (tid < TS) {
    size_t o = (size_t)bh * NN + pos0 + tid;
    pm[tid] = perm[o];
    wPs[tid] = wPg[o];
    wQs[tid] = wQg[o];
  }
  __syncthreads();

  // gather permuted tile into smem (float4; one 128B row per K4 lanes)
  const float4* fe4 = (const float4*)(feat + (size_t)bh * NN * K);
  float4* vs4 = (float4*)vs;
  for (int e = tid; e < TS * K4; e += 512) {
    int i = e / K4, q = e % K4;
    vs4[e] = fe4[(size_t)pm[i] * K4 + q];
  }
  __syncthreads();

  // coalesced write of gathered tile to featS
  float4* fs4 = (float4*)(featS + ((size_t)bh * NN + pos0) * K);
  for (int e = tid; e < TS * K4; e += 512) fs4[e] = vs4[e];

  // tile sums from smem
  int k = tid % K, r = tid / K;
  float aP = 0.f, aQ = 0.f;
  for (int i = r; i < TS; i += RS) {
    float v = vs[i * K + k];
    aP = fmaf(wPs[i], v, aP);
    aQ = fmaf(wQs[i], v, aQ);
  }
  redP[tid] = aP; redQ[tid] = aQ;
  __syncthreads();
  size_t tbP = ((size_t)(bh * 2)     * NT + tile) * (K + 1);
  size_t tbQ = ((size_t)(bh * 2 + 1) * NT + tile) * (K + 1);
  if (r == 0) {
    float sP = aP, sQ = aQ;
    #pragma unroll
    for (int j = 1; j < RS; ++j) { sP += redP[j * K + k]; sQ += redQ[j * K + k]; }
    tsum[tbP + k] = sP;
    tsum[tbQ + k] = sQ;
  }
  if (tid < 32) {
    float wa = 0.f, wb = 0.f;
    #pragma unroll
    for (int i = 0; i < TS / 32; ++i) {
      wa += wPs[tid + 32 * i];
      wb += wQs[tid + 32 * i];
    }
    #pragma unroll
    for (int o = 16; o; o >>= 1) {
      wa += __shfl_down_sync(0xffffffffu, wa, o);
      wb += __shfl_down_sync(0xffffffffu, wb, o);
    }
    if (tid == 0) { tsum[tbP + K] = wa; tsum[tbQ + K] = wb; }
  }
}

// ---------------- scan pass C: coalesced featS read + tile-local scans -----
template<int L>
__global__ void scanC_kernel() {
  constexpr int K = LP<L>::K;
  constexpr int K4 = K / 4;
  const float* featS = (L == 0) ? g_featS0 : g_featS1;
  const float* wPg = (L == 0) ? g_wP0 : g_wP1;
  const float* wQg = (L == 0) ? g_wQ0 : g_wQ1;
  const float* tsum = (L == 0) ? g_ts0 : g_ts1;
  float* pref = (L == 0) ? g_pref0 : g_pref1;
  __shared__ float vs[TS * K];
  __shared__ float wPs[TS], wQs[TS];
  int bh = blockIdx.x, tile = blockIdx.y, pos0 = tile * TS;
  int tid = threadIdx.x;
  if (tid < TS) {
    size_t o = (size_t)bh * NN + pos0 + tid;
    wPs[tid] = wPg[o];
    wQs[tid] = wQg[o];
  }
  const float4* fs4 = (const float4*)(featS + ((size_t)bh * NN + pos0) * K);
  float4* vs4 = (float4*)vs;
  for (int e = tid; e < TS * K4; e += 256) vs4[e] = fs4[e];
  __syncthreads();
  if (tid <= K) {
    int d = tid;
    size_t cb = (size_t)(bh * 2) * NT;
    float run = 0.f;
    for (int tt = 0; tt < tile; ++tt) run += tsum[(cb + tt) * (K + 1) + d];
    float* outP = pref + ((size_t)(bh * 2) * (NN + 1) + pos0) * (K + 1) + d;
    if (d < K) {
      for (int i = 0; i < TS; ++i) {
        outP[(size_t)i * (K + 1)] = run;
        run = fmaf(wPs[i], vs[i * K + d], run);
      }
    } else {
      for (int i = 0; i < TS; ++i) {
        outP[(size_t)i * (K + 1)] = run;
        run += wPs[i];
      }
    }
    if (tile == NT - 1)
      pref[((size_t)(bh * 2) * (NN + 1) + NN) * (K + 1) + d] = run;  // P total
  } else if (tid >= 128 && tid <= 128 + K) {
    int d = tid - 128;
    size_t cb = (size_t)(bh * 2 + 1) * NT;
    float run = 0.f;
    for (int tt = tile + 1; tt < NT; ++tt) run += tsum[(cb + tt) * (K + 1) + d];
    float* outQ = pref + ((size_t)(bh * 2 + 1) * (NN + 1) + pos0) * (K + 1) + d;
    if (d < K) {
      for (int i = TS - 1; i >= 0; --i) {
        run = fmaf(wQs[i], vs[i * K + d], run);
        outQ[(size_t)i * (K + 1)] = run;
      }
    } else {
      for (int i = TS - 1; i >= 0; --i) {
        run += wQs[i];
        outQ[(size_t)i * (K + 1)] = run;
      }
    }
    if (tile == NT - 1)
      pref[((size_t)(bh * 2 + 1) * (NN + 1) + NN) * (K + 1) + d] = 0.f;
  }
}

// ---------------- per-row combine (+ layer-1 norm partials for L==0) -------
template<int L>
__global__ void rows_kernel(const float* __restrict__ bias,
                            float* __restrict__ outext) {
  constexpr int K = LP<L>::K, H = LP<L>::H;
  constexpr bool ELU = (L == 0);
  constexpr int RPB = 128;
  const float* ssrc  = (L == 0) ? g_ssrc0 : g_ssrc1;
  const float* sortd = (L == 0) ? g_sortd0 : g_sortd1;
  const float* pref  = (L == 0) ? g_pref0 : g_pref1;
  const float* dmaxA = (L == 0) ? g_dmax0 : g_dmax1;
  float* out = (L == 0) ? g_cat : outext;

  int bh = blockIdx.x;
  __shared__ float sd[NN];
  __shared__ int   ms[RPB];
  __shared__ float al[RPB], be[RPB];
  __shared__ float bs[K];
  __shared__ float sred[8 * 32], sred2[8 * 32];
  for (int i = threadIdx.x; i < NN; i += 256) sd[i] = sortd[(size_t)bh * NN + i];
  const float* prefP = pref + (size_t)(bh * 2) * (NN + 1) * (K + 1);
  const float* prefQ = prefP + (size_t)(NN + 1) * (K + 1);
  if (threadIdx.x < K) bs[threadIdx.x] = bias[threadIdx.x];
  __syncthreads();

  float dmax = dmaxA[bh];
  int row0 = blockIdx.y * RPB;

  if (threadIdx.x < RPB) {
    int r = row0 + threadIdx.x;
    float s = ssrc[(size_t)bh * NN + r];
    float T = s + dmax;
    if (T > 0.f) { al[threadIdx.x] = 1.f; be[threadIdx.x] = expf(-0.8f * T); }
    else         { al[threadIdx.x] = expf(0.8f * T); be[threadIdx.x] = 1.f; }
    float thr = -s;
    int lo = 0, hi = NN;
    while (lo < hi) {
      int mid = (lo + hi) >> 1;
      if (sd[mid] > thr) lo = mid + 1; else hi = mid;
    }
    ms[threadIdx.x] = lo;
  }
  __syncthreads();

  int warp = threadIdx.x >> 5, lane = threadIdx.x & 31;
  int b = bh / H, h = bh % H;
  float sv = 0.f, sv2 = 0.f;   // layer-1 norm partials (L==0, lane = channel)
  for (int rr = warp; rr < RPB; rr += 8) {
    int r = row0 + rr;
    int m = ms[rr];
    float alpha = al[rr], beta = be[rr];
    const float* pP = prefP + (size_t)m * (K + 1);
    const float* pQ = prefQ + (size_t)m * (K + 1);
    float den = alpha * pP[K] + beta * pQ[K];
    float inv = 1.f / den;
    #pragma unroll
    for (int k = lane; k < K; k += 32) {
      float num = alpha * pP[k] + beta * pQ[k];
      float v = num * inv + bs[k];
      size_t oi = ((size_t)b * NN + r) * (size_t)(H * K) + (size_t)h * K + k;
      if (ELU) {
        v = (v > 0.f) ? v : (expf(v) - 1.f);
        out[oi] = v;
        sv += v; sv2 = fmaf(v, v, sv2);
      } else {
        out[oi] = v;
      }
    }
  }
  if (ELU) {
    sred[warp * 32 + lane] = sv;
    sred2[warp * 32 + lane] = sv2;
    __syncthreads();
    if (warp == 0) {
      float S = sv, S2 = sv2;
      #pragma unroll
      for (int w = 1; w < 8; ++w) { S += sred[w * 32 + lane]; S2 += sred2[w * 32 + lane]; }
      int c = h * 32 + lane;  // K == 32 for L == 0
      size_t o = (((size_t)b * 32 + blockIdx.y) * 128 + c) * 2;
      g_part1[o] = S; g_part1[o + 1] = S2;
    }
  }
}

// ---------------- launch ----------------------------------------------------
extern "C" void kernel_launch(void* const* d_in, const int* in_sizes, int n_in,
                              void* d_out, int out_size) {
  (void)in_sizes; (void)n_in; (void)out_size;
  const float* x      = (const float*)d_in[0];
  const float* w0     = (const float*)d_in[1];
  const float* a_src0 = (const float*)d_in[2];
  const float* a_dst0 = (const float*)d_in[3];
  const float* b0     = (const float*)d_in[4];
  const float* w1     = (const float*)d_in[5];
  const float* a_src1 = (const float*)d_in[6];
  const float* a_dst1 = (const float*)d_in[7];
  const float* b1     = (const float*)d_in[8];
  float* out = (float*)d_out;

  // ---- layer 0 ----
  stats_part0_kernel<<<dim3(NB, NSLAB), 256>>>(x);
  fold_kernel<0><<<NB, 128>>>(w0);
  gemm_kernel<0><<<dim3(NB, NN / 64), 256>>>(x, a_src0, a_dst0);
  sort_kernel<0><<<16, 1024>>>();
  scanA_kernel<0><<<dim3(16, NT), 512>>>();
  scanC_kernel<0><<<dim3(16, NT), 256>>>();
  rows_kernel<0><<<dim3(16, NN / 128), 256>>>(b0, nullptr);

  // ---- layer 1 ----
  fold_kernel<1><<<NB, 128>>>(w1);
  gemm_kernel<1><<<dim3(NB, NN / 32), 256>>>(nullptr, a_src1, a_dst1);
  sort_kernel<1><<<4, 1024>>>();
  scanA_kernel<1><<<dim3(4, NT), 512>>>();
  scanC_kernel<1><<<dim3(4, NT), 256>>>();
  rows_kernel<1><<<dim3(4, NN / 128), 256>>>(b1, out);
}

// round 15
// speedup vs baseline: 1.0314x; 1.0314x over previous
#include <cuda_runtime.h>
#include <math.h>

// ============================================================================
// GAT 2-layer forward, exact-math O(n log n) reformulation.
// softmax_j(LeakyReLU(s_i + d_j)) @ V via sorted-d tables:
//   P = forward prefix of e^{d-dmax}*v ; Q = reverse suffix of e^{0.2(d-dmax)}*v
// R15: R13 base (best: 121.3us). Single delta: sort caches d values in smem
//      so the output epilogue gathers from LDS instead of L2.
// ============================================================================

#define NB 4
#define NN 4096
#define EPSN 1e-5f
#define NT 32      // scan tiles per chain
#define TS 128     // scan tile size (NT*TS == NN)
#define NSLAB 16   // layer-0 stats slabs

template<int L> struct LP {
  static constexpr int CIN  = (L == 0) ? 64 : 128;
  static constexpr int H    = (L == 0) ? 4 : 1;
  static constexpr int K    = (L == 0) ? 32 : 64;
  static constexpr int COUT = H * K;
  static constexpr int SL   = (L == 0) ? NSLAB : 32;  // stats slabs
};

// ---------------- scratch (device globals; no allocation allowed) ----------
__device__ float  g_part0[NB * NSLAB * 64 * 2];
__device__ float  g_part1[NB * 32 * 128 * 2];
__device__ float  g_w0p[NB * 64 * 128], g_t0[NB * 128];
__device__ float  g_w1p[NB * 128 * 64], g_t1[NB * 64];
__device__ float  g_feat0[16 * NN * 32];
__device__ float  g_feat1[4 * NN * 64];
__device__ float  g_featS0[16 * NN * 32];
__device__ float  g_featS1[4 * NN * 64];
__device__ float  g_ssrc0[16 * NN], g_sdst0[16 * NN];
__device__ float  g_ssrc1[4 * NN],  g_sdst1[4 * NN];
__device__ float  g_sortd0[16 * NN];
__device__ int    g_perm0[16 * NN];
__device__ float  g_sortd1[4 * NN];
__device__ int    g_perm1[4 * NN];
__device__ float  g_dmax0[16], g_dmax1[4];
__device__ float  g_wP0[16 * NN], g_wQ0[16 * NN];
__device__ float  g_wP1[4 * NN],  g_wQ1[4 * NN];
__device__ float  g_ts0[32 * NT * 33];
__device__ float  g_ts1[8 * NT * 65];
__device__ float  g_pref0[(size_t)16 * 2 * (NN + 1) * 33];
__device__ float  g_pref1[(size_t)4  * 2 * (NN + 1) * 65];
__device__ float  g_cat[(size_t)NB * NN * 128];

// ---------------- layer-0 instance-norm stats: slab partials ---------------
__global__ void stats_part0_kernel(const float* __restrict__ x) {
  constexpr int C = 64;
  constexpr int RP = 256 / C;  // 4
  int b = blockIdx.x, slab = blockIdx.y;
  int c = threadIdx.x % C, rr = threadIdx.x / C;
  const float* p = x + ((size_t)b * NN + (size_t)slab * 256) * C;
  float s = 0.f, s2 = 0.f;
  for (int i = rr; i < 256; i += RP) {
    float v = p[(size_t)i * C + c];
    s += v; s2 = fmaf(v, v, s2);
  }
  __shared__ float sh[256], sh2[256];
  sh[threadIdx.x] = s; sh2[threadIdx.x] = s2;
  __syncthreads();
  if (rr == 0) {
    float S = s, S2 = s2;
    #pragma unroll
    for (int j = 1; j < RP; ++j) { S += sh[j * C + c]; S2 += sh2[j * C + c]; }
    size_t o = (((size_t)b * NSLAB + slab) * C + c) * 2;
    g_part0[o] = S; g_part0[o + 1] = S2;
  }
}

// ---------------- combine stats + fold instance-norm into weights ----------
template<int L>
__global__ void fold_kernel(const float* __restrict__ w) {
  constexpr int CIN = LP<L>::CIN, K = LP<L>::K, COUT = LP<L>::COUT, SL = LP<L>::SL;
  const float* part = (L == 0) ? g_part0 : g_part1;
  float* wp = (L == 0) ? g_w0p : g_w1p;
  float* tv = (L == 0) ? g_t0 : g_t1;
  __shared__ float mu[CIN], rs[CIN];
  int b = blockIdx.x, tid = threadIdx.x;
  if (tid < CIN) {
    double S = 0.0, S2 = 0.0;
    for (int slab = 0; slab < SL; ++slab) {
      size_t o = (((size_t)b * SL + slab) * CIN + tid) * 2;
      S += (double)part[o]; S2 += (double)part[o + 1];
    }
    double mean = S / NN;
    double var = S2 / NN - mean * mean;
    mu[tid] = (float)mean;
    rs[tid] = (float)(1.0 / sqrt(var + (double)EPSN));
  }
  __syncthreads();
  if (tid < COUT) {
    int h = tid / K, k = tid % K;
    float acc = 0.f;
    for (int c = 0; c < CIN; ++c) {
      float wv  = w[((size_t)h * CIN + c) * K + k];
      float wpv = wv * rs[c];
      wp[((size_t)b * CIN + c) * COUT + tid] = wpv;
      acc = fmaf(mu[c], wpv, acc);
    }
    tv[b * COUT + tid] = acc;
  }
}

// ---------------- GEMM (float4-x register-tiled) + fused s_src/s_dst -------
template<int L>
__global__ void gemm_kernel(const float* __restrict__ xext,
                            const float* __restrict__ a_src,
                            const float* __restrict__ a_dst) {
  constexpr int CIN = LP<L>::CIN, H = LP<L>::H, K = LP<L>::K, COUT = LP<L>::COUT;
  constexpr int ROWS = (L == 0) ? 64 : 32;
  constexpr int NC = COUT / 4;
  constexpr int NR = 256 / NC;
  constexpr int RT = ROWS / NR;
  constexpr int G  = NC / H;
  const float* x  = (L == 0) ? xext : g_cat;
  const float* wp = (L == 0) ? g_w0p : g_w1p;
  const float* tv = (L == 0) ? g_t0 : g_t1;
  float* feat = (L == 0) ? g_feat0 : g_feat1;
  float* ssrc = (L == 0) ? g_ssrc0 : g_ssrc1;
  float* sdst = (L == 0) ? g_sdst0 : g_sdst1;
  __shared__ float ws[CIN * COUT];
  __shared__ float xs[ROWS * CIN];
  int b = blockIdx.x, bt = blockIdx.y;
  int tid = threadIdx.x;
  const float4* wsrc = (const float4*)(wp + (size_t)b * CIN * COUT);
  for (int i = tid; i < CIN * COUT / 4; i += 256) ((float4*)ws)[i] = wsrc[i];
  const float4* xsrc = (const float4*)(x + ((size_t)b * NN + (size_t)bt * ROWS) * CIN);
  for (int i = tid; i < ROWS * CIN / 4; i += 256) ((float4*)xs)[i] = xsrc[i];
  __syncthreads();
  int tc = tid % NC, tr = tid / NC;
  int col0 = tc * 4, r0 = tr * RT;
  float4 tv4 = *(const float4*)(tv + b * COUT + col0);
  float acc[RT][4];
  #pragma unroll
  for (int i = 0; i < RT; ++i) {
    acc[i][0] = -tv4.x; acc[i][1] = -tv4.y; acc[i][2] = -tv4.z; acc[i][3] = -tv4.w;
  }
  const float4* wsv = (const float4*)ws;
  const float4* xsv = (const float4*)xs;
  #pragma unroll 4
  for (int c = 0; c < CIN; c += 4) {
    float4 w0 = wsv[(c + 0) * NC + tc];
    float4 w1 = wsv[(c + 1) * NC + tc];
    float4 w2 = wsv[(c + 2) * NC + tc];
    float4 w3 = wsv[(c + 3) * NC + tc];
    #pragma unroll
    for (int i = 0; i < RT; ++i) {
      float4 xv = xsv[(r0 + i) * (CIN / 4) + (c >> 2)];
      acc[i][0] = fmaf(xv.x, w0.x, acc[i][0]);
      acc[i][1] = fmaf(xv.x, w0.y, acc[i][1]);
      acc[i][2] = fmaf(xv.x, w0.z, acc[i][2]);
      acc[i][3] = fmaf(xv.x, w0.w, acc[i][3]);
      acc[i][0] = fmaf(xv.y, w1.x, acc[i][0]);
      acc[i][1] = fmaf(xv.y, w1.y, acc[i][1]);
      acc[i][2] = fmaf(xv.y, w1.z, acc[i][2]);
      acc[i][3] = fmaf(xv.y, w1.w, acc[i][3]);
      acc[i][0] = fmaf(xv.z, w2.x, acc[i][0]);
      acc[i][1] = fmaf(xv.z, w2.y, acc[i][1]);
      acc[i][2] = fmaf(xv.z, w2.z, acc[i][2]);
      acc[i][3] = fmaf(xv.z, w2.w, acc[i][3]);
      acc[i][0] = fmaf(xv.w, w3.x, acc[i][0]);
      acc[i][1] = fmaf(xv.w, w3.y, acc[i][1]);
      acc[i][2] = fmaf(xv.w, w3.z, acc[i][2]);
      acc[i][3] = fmaf(xv.w, w3.w, acc[i][3]);
    }
  }
  int h = col0 / K, k0 = col0 % K;
  float4 as4 = *(const float4*)(a_src + col0);
  float4 ad4 = *(const float4*)(a_dst + col0);
  int nbase = bt * ROWS + r0;
  float* fo = feat + (((size_t)b * H + h) * NN + nbase) * K + k0;
  size_t sbase = ((size_t)b * H + h) * NN + nbase;
  #pragma unroll
  for (int i = 0; i < RT; ++i) {
    *(float4*)(fo + (size_t)i * K) = make_float4(acc[i][0], acc[i][1], acc[i][2], acc[i][3]);
    float s1 = acc[i][0] * as4.x + acc[i][1] * as4.y + acc[i][2] * as4.z + acc[i][3] * as4.w;
    float s2 = acc[i][0] * ad4.x + acc[i][1] * ad4.y + acc[i][2] * ad4.z + acc[i][3] * ad4.w;
    #pragma unroll
    for (int off = 1; off < G; off <<= 1) {
      s1 += __shfl_xor_sync(0xffffffffu, s1, off);
      s2 += __shfl_xor_sync(0xffffffffu, s2, off);
    }
    if ((tc & (G - 1)) == 0) {
      ssrc[sbase + i] = s1;
      sdst[sbase + i] = s2;
    }
  }
}

// ---------------- single-pass counting sort (4096 buckets, 1024 thr) -------
// d values cached in smem so the output epilogue gathers via LDS, not L2.
template<int L>
__global__ void sort_kernel() {
  constexpr int BT = 1024, IPT = NN / BT;  // 4
  const float* sdstA = (L == 0) ? g_sdst0 : g_sdst1;
  float* sortd = (L == 0) ? g_sortd0 : g_sortd1;
  int*   perm  = (L == 0) ? g_perm0 : g_perm1;
  float* wP = (L == 0) ? g_wP0 : g_wP1;
  float* wQ = (L == 0) ? g_wQ0 : g_wQ1;
  float* dmaxA = (L == 0) ? g_dmax0 : g_dmax1;

  __shared__ int   cnt[NN];
  __shared__ int   perm_s[NN];
  __shared__ float d_s[NN];
  __shared__ float wred[64];
  __shared__ int   wsum[32];
  __shared__ float s_mn, s_mx;

  int bh = blockIdx.x;
  int tid = threadIdx.x, lane = tid & 31, wid = tid >> 5;
  const float* src = sdstA + (size_t)bh * NN;

  float d[IPT];
  int base = tid * IPT;
  #pragma unroll
  for (int i = 0; i < IPT; ++i) {
    d[i] = src[base + i];
    d_s[base + i] = d[i];
  }

  float mn = d[0], mx = d[0];
  #pragma unroll
  for (int i = 1; i < IPT; ++i) { mn = fminf(mn, d[i]); mx = fmaxf(mx, d[i]); }
  #pragma unroll
  for (int o = 16; o; o >>= 1) {
    mn = fminf(mn, __shfl_xor_sync(0xffffffffu, mn, o));
    mx = fmaxf(mx, __shfl_xor_sync(0xffffffffu, mx, o));
  }
  if (lane == 0) { wred[wid] = mn; wred[wid + 32] = mx; }
  for (int i = tid; i < NN; i += BT) cnt[i] = 0;
  __syncthreads();
  if (tid == 0) {
    float m1 = wred[0], m2 = wred[32];
    #pragma unroll
    for (int i = 1; i < 32; ++i) { m1 = fminf(m1, wred[i]); m2 = fmaxf(m2, wred[i + 32]); }
    s_mn = m1; s_mx = m2;
    dmaxA[bh] = m2;
  }
  __syncthreads();
  float dmax = s_mx;
  float scale = (float)(NN - 1) / fmaxf(s_mx - s_mn, 1e-30f);

  int bkt[IPT];
  #pragma unroll
  for (int i = 0; i < IPT; ++i) {
    int bb = (int)((dmax - d[i]) * scale);
    bkt[i] = min(max(bb, 0), NN - 1);
    atomicAdd(&cnt[bkt[i]], 1);
  }
  __syncthreads();

  int base4 = tid * IPT;
  int c4[IPT]; int tsm = 0;
  #pragma unroll
  for (int j = 0; j < IPT; ++j) { c4[j] = cnt[base4 + j]; tsm += c4[j]; }
  int pre = tsm;
  #pragma unroll
  for (int o = 1; o < 32; o <<= 1) {
    int nv = __shfl_up_sync(0xffffffffu, pre, o);
    if (lane >= o) pre += nv;
  }
  pre -= tsm;
  if (lane == 31) wsum[wid] = pre + tsm;
  __syncthreads();
  if (tid < 32) {
    int v = wsum[tid];
    int iv = v;
    #pragma unroll
    for (int o = 1; o < 32; o <<= 1) {
      int nv = __shfl_up_sync(0xffffffffu, iv, o);
      if (tid >= o) iv += nv;
    }
    wsum[tid] = iv - v;
  }
  __syncthreads();
  int run = wsum[wid] + pre;
  #pragma unroll
  for (int j = 0; j < IPT; ++j) { cnt[base4 + j] = run; run += c4[j]; }
  __syncthreads();

  #pragma unroll
  for (int i = 0; i < IPT; ++i) {
    int r = atomicAdd(&cnt[bkt[i]], 1);
    perm_s[r] = base + i;
  }
  __syncthreads();

  for (int r = tid; r < NN; r += BT) {
    int p = perm_s[r];
    float dv = d_s[p];
    size_t o = (size_t)bh * NN + r;
    sortd[o] = dv;
    perm[o]  = p;
    float e = dv - dmax;
    wP[o] = expf(e);
    wQ[o] = expf(0.2f * e);
  }
}

// ---------------- scan pass A (512 thr): gather -> smem, sums, write featS -
template<int L>
__global__ void scanA_kernel() {
  constexpr int K = LP<L>::K;
  constexpr int K4 = K / 4;
  constexpr int RS = 512 / K;  // 16 / 8
  const float* feat = (L == 0) ? g_feat0 : g_feat1;
  const int*   perm = (L == 0) ? g_perm0 : g_perm1;
  const float* wPg = (L == 0) ? g_wP0 : g_wP1;
  const float* wQg = (L == 0) ? g_wQ0 : g_wQ1;
  float* featS = (L == 0) ? g_featS0 : g_featS1;
  float* tsum = (L == 0) ? g_ts0 : g_ts1;

  __shared__ float vs[TS * K];
  __shared__ float wPs[TS], wQs[TS];
  __shared__ int pm[TS];
  __shared__ float redP[512], redQ[512];

  int bh = blockIdx.x, tile = blockIdx.y, pos0 = tile * TS;
  int tid = threadIdx.x;
  if (tid < TS) {
    size_t o = (size_t)bh * NN + pos0 + tid;
    pm[tid] = perm[o];
    wPs[tid] = wPg[o];
    wQs[tid] = wQg[o];
  }
  __syncthreads();

  // gather permuted tile into smem (float4; one 128B row per K4 lanes)
  const float4* fe4 = (const float4*)(feat + (size_t)bh * NN * K);
  float4* vs4 = (float4*)vs;
  for (int e = tid; e < TS * K4; e += 512) {
    int i = e / K4, q = e % K4;
    vs4[e] = fe4[(size_t)pm[i] * K4 + q];
  }
  __syncthreads();

  // coalesced write of gathered tile to featS
  float4* fs4 = (float4*)(featS + ((size_t)bh * NN + pos0) * K);
  for (int e = tid; e < TS * K4; e += 512) fs4[e] = vs4[e];

  // tile sums from smem
  int k = tid % K, r = tid / K;
  float aP = 0.f, aQ = 0.f;
  for (int i = r; i < TS; i += RS) {
    float v = vs[i * K + k];
    aP = fmaf(wPs[i], v, aP);
    aQ = fmaf(wQs[i], v, aQ);
  }
  redP[tid] = aP; redQ[tid] = aQ;
  __syncthreads();
  size_t tbP = ((size_t)(bh * 2)     * NT + tile) * (K + 1);
  size_t tbQ = ((size_t)(bh * 2 + 1) * NT + tile) * (K + 1);
  if (r == 0) {
    float sP = aP, sQ = aQ;
    #pragma unroll
    for (int j = 1; j < RS; ++j) { sP += redP[j * K + k]; sQ += redQ[j * K + k]; }
    tsum[tbP + k] = sP;
    tsum[tbQ + k] = sQ;
  }
  if (tid < 32) {
    float wa = 0.f, wb = 0.f;
    #pragma unroll
    for (int i = 0; i < TS / 32; ++i) {
      wa += wPs[tid + 32 * i];
      wb += wQs[tid + 32 * i];
    }
    #pragma unroll
    for (int o = 16; o; o >>= 1) {
      wa += __shfl_down_sync(0xffffffffu, wa, o);
      wb += __shfl_down_sync(0xffffffffu, wb, o);
    }
    if (tid == 0) { tsum[tbP + K] = wa; tsum[tbQ + K] = wb; }
  }
}

// ---------------- scan pass C: coalesced featS read + tile-local scans -----
template<int L>
__global__ void scanC_kernel() {
  constexpr int K = LP<L>::K;
  constexpr int K4 = K / 4;
  const float* featS = (L == 0) ? g_featS0 : g_featS1;
  const float* wPg = (L == 0) ? g_wP0 : g_wP1;
  const float* wQg = (L == 0) ? g_wQ0 : g_wQ1;
  const float* tsum = (L == 0) ? g_ts0 : g_ts1;
  float* pref = (L == 0) ? g_pref0 : g_pref1;
  __shared__ float vs[TS * K];
  __shared__ float wPs[TS], wQs[TS];
  int bh = blockIdx.x, tile = blockIdx.y, pos0 = tile * TS;
  int tid = threadIdx.x;
  if (tid < TS) {
    size_t o = (size_t)bh * NN + pos0 + tid;
    wPs[tid] = wPg[o];
    wQs[tid] = wQg[o];
  }
  const float4* fs4 = (const float4*)(featS + ((size_t)bh * NN + pos0) * K);
  float4* vs4 = (float4*)vs;
  for (int e = tid; e < TS * K4; e += 256) vs4[e] = fs4[e];
  __syncthreads();
  if (tid <= K) {
    int d = tid;
    size_t cb = (size_t)(bh * 2) * NT;
    float run = 0.f;
    for (int tt = 0; tt < tile; ++tt) run += tsum[(cb + tt) * (K + 1) + d];
    float* outP = pref + ((size_t)(bh * 2) * (NN + 1) + pos0) * (K + 1) + d;
    if (d < K) {
      for (int i = 0; i < TS; ++i) {
        outP[(size_t)i * (K + 1)] = run;
        run = fmaf(wPs[i], vs[i * K + d], run);
      }
    } else {
      for (int i = 0; i < TS; ++i) {
        outP[(size_t)i * (K + 1)] = run;
        run += wPs[i];
      }
    }
    if (tile == NT - 1)
      pref[((size_t)(bh * 2) * (NN + 1) + NN) * (K + 1) + d] = run;  // P total
  } else if (tid >= 128 && tid <= 128 + K) {
    int d = tid - 128;
    size_t cb = (size_t)(bh * 2 + 1) * NT;
    float run = 0.f;
    for (int tt = tile + 1; tt < NT; ++tt) run += tsum[(cb + tt) * (K + 1) + d];
    float* outQ = pref + ((size_t)(bh * 2 + 1) * (NN + 1) + pos0) * (K + 1) + d;
    if (d < K) {
      for (int i = TS - 1; i >= 0; --i) {
        run = fmaf(wQs[i], vs[i * K + d], run);
        outQ[(size_t)i * (K + 1)] = run;
      }
    } else {
      for (int i = TS - 1; i >= 0; --i) {
        run += wQs[i];
        outQ[(size_t)i * (K + 1)] = run;
      }
    }
    if (tile == NT - 1)
      pref[((size_t)(bh * 2 + 1) * (NN + 1) + NN) * (K + 1) + d] = 0.f;
  }
}

// ---------------- per-row combine (+ layer-1 norm partials for L==0) -------
template<int L>
__global__ void rows_kernel(const float* __restrict__ bias,
                            float* __restrict__ outext) {
  constexpr int K = LP<L>::K, H = LP<L>::H;
  constexpr bool ELU = (L == 0);
  constexpr int RPB = 128;
  const float* ssrc  = (L == 0) ? g_ssrc0 : g_ssrc1;
  const float* sortd = (L == 0) ? g_sortd0 : g_sortd1;
  const float* pref  = (L == 0) ? g_pref0 : g_pref1;
  const float* dmaxA = (L == 0) ? g_dmax0 : g_dmax1;
  float* out = (L == 0) ? g_cat : outext;

  int bh = blockIdx.x;
  __shared__ float sd[NN];
  __shared__ int   ms[RPB];
  __shared__ float al[RPB], be[RPB];
  __shared__ float bs[K];
  __shared__ float sred[8 * 32], sred2[8 * 32];
  for (int i = threadIdx.x; i < NN; i += 256) sd[i] = sortd[(size_t)bh * NN + i];
  const float* prefP = pref + (size_t)(bh * 2) * (NN + 1) * (K + 1);
  const float* prefQ = prefP + (size_t)(NN + 1) * (K + 1);
  if (threadIdx.x < K) bs[threadIdx.x] = bias[threadIdx.x];
  __syncthreads();

  float dmax = dmaxA[bh];
  int row0 = blockIdx.y * RPB;

  if (threadIdx.x < RPB) {
    int r = row0 + threadIdx.x;
    float s = ssrc[(size_t)bh * NN + r];
    float T = s + dmax;
    if (T > 0.f) { al[threadIdx.x] = 1.f; be[threadIdx.x] = expf(-0.8f * T); }
    else         { al[threadIdx.x] = expf(0.8f * T); be[threadIdx.x] = 1.f; }
    float thr = -s;
    int lo = 0, hi = NN;
    while (lo < hi) {
      int mid = (lo + hi) >> 1;
      if (sd[mid] > thr) lo = mid + 1; else hi = mid;
    }
    ms[threadIdx.x] = lo;
  }
  __syncthreads();

  int warp = threadIdx.x >> 5, lane = threadIdx.x & 31;
  int b = bh / H, h = bh % H;
  float sv = 0.f, sv2 = 0.f;   // layer-1 norm partials (L==0, lane = channel)
  for (int rr = warp; rr < RPB; rr += 8) {
    int r = row0 + rr;
    int m = ms[rr];
    float alpha = al[rr], beta = be[rr];
    const float* pP = prefP + (size_t)m * (K + 1);
    const float* pQ = prefQ + (size_t)m * (K + 1);
    float den = alpha * pP[K] + beta * pQ[K];
    float inv = 1.f / den;
    #pragma unroll
    for (int k = lane; k < K; k += 32) {
      float num = alpha * pP[k] + beta * pQ[k];
      float v = num * inv + bs[k];
      size_t oi = ((size_t)b * NN + r) * (size_t)(H * K) + (size_t)h * K + k;
      if (ELU) {
        v = (v > 0.f) ? v : (expf(v) - 1.f);
        out[oi] = v;
        sv += v; sv2 = fmaf(v, v, sv2);
      } else {
        out[oi] = v;
      }
    }
  }
  if (ELU) {
    sred[warp * 32 + lane] = sv;
    sred2[warp * 32 + lane] = sv2;
    __syncthreads();
    if (warp == 0) {
      float S = sv, S2 = sv2;
      #pragma unroll
      for (int w = 1; w < 8; ++w) { S += sred[w * 32 + lane]; S2 += sred2[w * 32 + lane]; }
      int c = h * 32 + lane;  // K == 32 for L == 0
      size_t o = (((size_t)b * 32 + blockIdx.y) * 128 + c) * 2;
      g_part1[o] = S; g_part1[o + 1] = S2;
    }
  }
}

// ---------------- launch ----------------------------------------------------
extern "C" void kernel_launch(void* const* d_in, const int* in_sizes, int n_in,
                              void* d_out, int out_size) {
  (void)in_sizes; (void)n_in; (void)out_size;
  const float* x      = (const float*)d_in[0];
  const float* w0     = (const float*)d_in[1];
  const float* a_src0 = (const float*)d_in[2];
  const float* a_dst0 = (const float*)d_in[3];
  const float* b0     = (const float*)d_in[4];
  const float* w1     = (const float*)d_in[5];
  const float* a_src1 = (const float*)d_in[6];
  const float* a_dst1 = (const float*)d_in[7];
  const float* b1     = (const float*)d_in[8];
  float* out = (float*)d_out;

  // ---- layer 0 ----
  stats_part0_kernel<<<dim3(NB, NSLAB), 256>>>(x);
  fold_kernel<0><<<NB, 128>>>(w0);
  gemm_kernel<0><<<dim3(NB, NN / 64), 256>>>(x, a_src0, a_dst0);
  sort_kernel<0><<<16, 1024>>>();
  scanA_kernel<0><<<dim3(16, NT), 512>>>();
  scanC_kernel<0><<<dim3(16, NT), 256>>>();
  rows_kernel<0><<<dim3(16, NN / 128), 256>>>(b0, nullptr);

  // ---- layer 1 ----
  fold_kernel<1><<<NB, 128>>>(w1);
  gemm_kernel<1><<<dim3(NB, NN / 32), 256>>>(nullptr, a_src1, a_dst1);
  sort_kernel<1><<<4, 1024>>>();
  scanA_kernel<1><<<dim3(4, NT), 512>>>();
  scanC_kernel<1><<<dim3(4, NT), 256>>>();
  rows_kernel<1><<<dim3(4, NN / 128), 256>>>(b1, out);
}